// round 4
// baseline (speedup 1.0000x reference)
#include <cuda_runtime.h>

typedef unsigned long long u64;

// ---- packed f32x2 helpers (sm_103a) ----
__device__ __forceinline__ u64 pack2(float lo, float hi) {
    u64 r; asm("mov.b64 %0, {%1, %2};" : "=l"(r) : "f"(lo), "f"(hi)); return r;
}
__device__ __forceinline__ void unpack2(u64 v, float& lo, float& hi) {
    asm("mov.b64 {%0, %1}, %2;" : "=f"(lo), "=f"(hi) : "l"(v));
}
__device__ __forceinline__ u64 fma2(u64 a, u64 b, u64 c) {
    u64 d; asm("fma.rn.f32x2 %0, %1, %2, %3;" : "=l"(d) : "l"(a), "l"(b), "l"(c));
    return d;
}

#define TPB 256
#define MAX_PAIRS 512          // palette-pair capacity (M up to 1024)

// Fixed-point accumulator: integer atomics commute exactly -> deterministic.
#define SUM_SCALE 4294967296.0 // 2^32

__device__ unsigned long long g_sum = 0ULL;
__device__ unsigned int g_count = 0u;

// Palette stored as PAIRS of entries packed in f32x2 lanes:
//   s_xy[k] = { pack2(px_{2k}, px_{2k+1}), pack2(py_{2k}, py_{2k+1}) }
//   s_zc[k] = { pack2(pz_{2k}, pz_{2k+1}), pack2(c_{2k},  c_{2k+1}) }
// with c = 0.5*(px^2+py^2+pz^2).
// Per point: splat (-x,-x),(-y,-y),(-z,-z) once; per pair k:
//   score2 = fma2(sx, xx, fma2(sy, yy, fma2(sz, zz, cc)))
// d = sqrt(max(|x|^2 + 2*min_score, 0)).
// One point per thread -> 4096 warps (27.7/SM) for latency hiding.

__global__ void __launch_bounds__(TPB)
ncd_fused(const float* __restrict__ pts, const float* __restrict__ pal,
          float* __restrict__ out, int N, int M)
{
    __shared__ ulonglong2 s_xy[MAX_PAIRS];
    __shared__ ulonglong2 s_zc[MAX_PAIRS];
    __shared__ float s_warp[TPB / 32];
    __shared__ bool s_last;

    const int tid = threadIdx.x;
    const int npair = (M + 1) >> 1;

    // Build packed palette pairs in shared.
    for (int k = tid; k < npair; k += TPB) {
        const int j0 = 2 * k;
        const int j1 = (2 * k + 1 < M) ? (2 * k + 1) : j0;  // dup tail if M odd
        const float px0 = pal[3 * j0 + 0], py0 = pal[3 * j0 + 1], pz0 = pal[3 * j0 + 2];
        const float px1 = pal[3 * j1 + 0], py1 = pal[3 * j1 + 1], pz1 = pal[3 * j1 + 2];
        const float c0 = 0.5f * (px0 * px0 + py0 * py0 + pz0 * pz0);
        const float c1 = 0.5f * (px1 * px1 + py1 * py1 + pz1 * pz1);
        s_xy[k] = make_ulonglong2(pack2(px0, px1), pack2(py0, py1));
        s_zc[k] = make_ulonglong2(pack2(pz0, pz1), pack2(c0, c1));
    }
    __syncthreads();

    float tsum = 0.0f;
    const long long i = (long long)blockIdx.x * TPB + tid;

    if (i < (long long)N) {
        const float x = pts[i * 3 + 0];
        const float y = pts[i * 3 + 1];
        const float z = pts[i * 3 + 2];

        const u64 sx = pack2(-x, -x), sy = pack2(-y, -y), sz = pack2(-z, -z);
        const float nrm = __fmaf_rn(x, x, __fmaf_rn(y, y, z * z));

        // Two independent min chains (2 pairs per iteration).
        float ma = 1e30f, mb = 1e30f;

        int k = 0;
        #pragma unroll 4
        for (; k + 2 <= npair; k += 2) {
            const ulonglong2 a0 = s_xy[k];
            const ulonglong2 b0 = s_zc[k];
            const ulonglong2 a1 = s_xy[k + 1];
            const ulonglong2 b1 = s_zc[k + 1];
            const u64 s0 = fma2(sx, a0.x, fma2(sy, a0.y, fma2(sz, b0.x, b0.y)));
            const u64 s1 = fma2(sx, a1.x, fma2(sy, a1.y, fma2(sz, b1.x, b1.y)));
            float lo, hi;
            unpack2(s0, lo, hi);
            ma = fminf(ma, fminf(lo, hi));
            unpack2(s1, lo, hi);
            mb = fminf(mb, fminf(lo, hi));
        }
        for (; k < npair; k++) {   // tail (not taken for M=128)
            const ulonglong2 a0 = s_xy[k];
            const ulonglong2 b0 = s_zc[k];
            const u64 s0 = fma2(sx, a0.x, fma2(sy, a0.y, fma2(sz, b0.x, b0.y)));
            float lo, hi;
            unpack2(s0, lo, hi);
            ma = fminf(ma, fminf(lo, hi));
        }

        const float m = fminf(ma, mb);
        tsum = sqrtf(fmaxf(__fmaf_rn(2.0f, m, nrm), 0.0f));
    }

    // ---- block reduction (deterministic order within block) ----
    #pragma unroll
    for (int o = 16; o; o >>= 1) tsum += __shfl_down_sync(0xFFFFFFFFu, tsum, o);
    if ((tid & 31) == 0) s_warp[tid >> 5] = tsum;
    __syncthreads();

    if (tid == 0) {
        float partial = 0.0f;
        #pragma unroll
        for (int w = 0; w < TPB / 32; w++) partial += s_warp[w];
        // fixed-point accumulate: exact integer adds -> order-independent
        const unsigned long long q = (unsigned long long)((double)partial * SUM_SCALE);
        atomicAdd(&g_sum, q);
        __threadfence();
        const unsigned int prev = atomicAdd(&g_count, 1u);
        s_last = (prev == gridDim.x - 1);
    }
    __syncthreads();

    if (s_last && tid == 0) {
        __threadfence();
        const unsigned long long total = atomicAdd(&g_sum, 0ULL);
        out[0] = (float)(((double)total / SUM_SCALE) / (double)N);
        // reset for next graph replay
        g_sum = 0ULL;
        g_count = 0u;
    }
}

extern "C" void kernel_launch(void* const* d_in, const int* in_sizes, int n_in,
                              void* d_out, int out_size)
{
    const float* pts = (const float*)d_in[0];   // output_colors (N,3)
    const float* pal = (const float*)d_in[1];   // target_palette (M,3)
    float* out = (float*)d_out;

    const int N = in_sizes[0] / 3;
    int M = in_sizes[1] / 3;
    if (M > 2 * MAX_PAIRS) M = 2 * MAX_PAIRS;   // dataset has M=128

    long long blocks_ll = ((long long)N + TPB - 1) / TPB;  // N=131072 -> 512 blocks
    if (blocks_ll < 1) blocks_ll = 1;
    if (blocks_ll > 1048576) blocks_ll = 1048576;
    const int blocks = (int)blocks_ll;

    ncd_fused<<<blocks, TPB>>>(pts, pal, out, N, M);
}

// round 5
// speedup vs baseline: 1.1696x; 1.1696x over previous
#include <cuda_runtime.h>

typedef unsigned long long u64;

// ---- packed f32x2 helpers (sm_103a) ----
__device__ __forceinline__ u64 pack2(float lo, float hi) {
    u64 r; asm("mov.b64 %0, {%1, %2};" : "=l"(r) : "f"(lo), "f"(hi)); return r;
}
__device__ __forceinline__ void unpack2(u64 v, float& lo, float& hi) {
    asm("mov.b64 {%0, %1}, %2;" : "=f"(lo), "=f"(hi) : "l"(v));
}
__device__ __forceinline__ u64 fma2(u64 a, u64 b, u64 c) {
    u64 d; asm("fma.rn.f32x2 %0, %1, %2, %3;" : "=l"(d) : "l"(a), "l"(b), "l"(c));
    return d;
}

#define TPB 256
#define PPT 2
#define MAX_PAIRS 512          // palette-pair capacity (M up to 1024)

// Fixed-point accumulator: integer atomics commute exactly -> deterministic.
#define SUM_SCALE 4294967296.0 // 2^32

__device__ unsigned long long g_sum = 0ULL;
__device__ unsigned int g_count = 0u;

// Palette stored as PAIRS of entries packed in f32x2 lanes:
//   s_xy[k] = { pack2(px_{2k}, px_{2k+1}), pack2(py_{2k}, py_{2k+1}) }
//   s_zc[k] = { pack2(pz_{2k}, pz_{2k+1}), pack2(c_{2k},  c_{2k+1}) }
// with c = 0.5*(px^2+py^2+pz^2).
// score = c - x*px - y*py - z*pz;  d = sqrt(max(|x|^2 + 2*min_score, 0))

__global__ void __launch_bounds__(TPB, 2)
ncd_fused(const float* __restrict__ pts, const float* __restrict__ pal,
          float* __restrict__ out, int N, int M)
{
    __shared__ ulonglong2 s_xy[MAX_PAIRS];
    __shared__ ulonglong2 s_zc[MAX_PAIRS];
    __shared__ float s_warp[TPB / 32];
    __shared__ bool s_last;

    const int tid = threadIdx.x;
    const int npair = (M + 1) >> 1;

    for (int k = tid; k < npair; k += TPB) {
        const int j0 = 2 * k;
        const int j1 = (2 * k + 1 < M) ? (2 * k + 1) : j0;  // dup tail if M odd
        const float px0 = pal[3 * j0 + 0], py0 = pal[3 * j0 + 1], pz0 = pal[3 * j0 + 2];
        const float px1 = pal[3 * j1 + 0], py1 = pal[3 * j1 + 1], pz1 = pal[3 * j1 + 2];
        const float c0 = 0.5f * (px0 * px0 + py0 * py0 + pz0 * pz0);
        const float c1 = 0.5f * (px1 * px1 + py1 * py1 + pz1 * pz1);
        s_xy[k] = make_ulonglong2(pack2(px0, px1), pack2(py0, py1));
        s_zc[k] = make_ulonglong2(pack2(pz0, pz1), pack2(c0, c1));
    }
    __syncthreads();

    float tsum = 0.0f;
    const long long base = ((long long)blockIdx.x * TPB + tid) * PPT;

    if (base < (long long)N) {
        const bool v1 = (base + 1 < (long long)N);

        // 6 floats via 3x float2 (base even -> 8B aligned).
        float x0, y0, z0, x1, y1, z1;
        {
            const float2* p2 = (const float2*)(pts + base * 3);
            const float2 f0 = p2[0];
            x0 = f0.x; y0 = f0.y;
            if (v1) {
                const float2 f1 = p2[1];
                const float2 f2 = p2[2];
                z0 = f1.x; x1 = f1.y; y1 = f2.x; z1 = f2.y;
            } else {
                z0 = pts[base * 3 + 2];
                x1 = x0; y1 = y0; z1 = z0;
            }
        }

        const u64 sx0 = pack2(-x0, -x0), sy0 = pack2(-y0, -y0), sz0 = pack2(-z0, -z0);
        const u64 sx1 = pack2(-x1, -x1), sy1 = pack2(-y1, -y1), sz1 = pack2(-z1, -z1);
        const float n0 = __fmaf_rn(x0, x0, __fmaf_rn(y0, y0, z0 * z0));
        const float n1 = __fmaf_rn(x1, x1, __fmaf_rn(y1, y1, z1 * z1));

        // 2 independent min accumulators per point.
        float m0a = 1e30f, m0b = 1e30f, m1a = 1e30f, m1b = 1e30f;

        if (M == 128) {
            // Specialized: fixed trip count, full unroll -> immediate LDS
            // offsets, no index math, no branches, max load batching.
            #pragma unroll
            for (int k = 0; k < 64; k += 2) {
                {
                    const ulonglong2 a = s_xy[k];
                    const ulonglong2 b = s_zc[k];
                    const u64 s0 = fma2(sx0, a.x, fma2(sy0, a.y, fma2(sz0, b.x, b.y)));
                    const u64 s1 = fma2(sx1, a.x, fma2(sy1, a.y, fma2(sz1, b.x, b.y)));
                    float lo, hi;
                    unpack2(s0, lo, hi);
                    m0a = fminf(m0a, fminf(lo, hi));
                    unpack2(s1, lo, hi);
                    m1a = fminf(m1a, fminf(lo, hi));
                }
                {
                    const ulonglong2 a = s_xy[k + 1];
                    const ulonglong2 b = s_zc[k + 1];
                    const u64 s0 = fma2(sx0, a.x, fma2(sy0, a.y, fma2(sz0, b.x, b.y)));
                    const u64 s1 = fma2(sx1, a.x, fma2(sy1, a.y, fma2(sz1, b.x, b.y)));
                    float lo, hi;
                    unpack2(s0, lo, hi);
                    m0b = fminf(m0b, fminf(lo, hi));
                    unpack2(s1, lo, hi);
                    m1b = fminf(m1b, fminf(lo, hi));
                }
            }
        } else {
            #pragma unroll 4
            for (int k = 0; k < npair; k++) {
                const ulonglong2 a = s_xy[k];
                const ulonglong2 b = s_zc[k];
                const u64 s0 = fma2(sx0, a.x, fma2(sy0, a.y, fma2(sz0, b.x, b.y)));
                const u64 s1 = fma2(sx1, a.x, fma2(sy1, a.y, fma2(sz1, b.x, b.y)));
                float lo, hi;
                unpack2(s0, lo, hi);
                m0a = fminf(m0a, fminf(lo, hi));
                unpack2(s1, lo, hi);
                m1a = fminf(m1a, fminf(lo, hi));
            }
        }

        const float m0 = fminf(m0a, m0b);
        const float m1 = fminf(m1a, m1b);
        tsum = sqrtf(fmaxf(__fmaf_rn(2.0f, m0, n0), 0.0f));
        if (v1) tsum += sqrtf(fmaxf(__fmaf_rn(2.0f, m1, n1), 0.0f));
    }

    // ---- block reduction (deterministic order within block) ----
    #pragma unroll
    for (int o = 16; o; o >>= 1) tsum += __shfl_down_sync(0xFFFFFFFFu, tsum, o);
    if ((tid & 31) == 0) s_warp[tid >> 5] = tsum;
    __syncthreads();

    if (tid == 0) {
        float partial = 0.0f;
        #pragma unroll
        for (int w = 0; w < TPB / 32; w++) partial += s_warp[w];
        // fixed-point accumulate: exact integer adds -> order-independent
        const unsigned long long q = (unsigned long long)((double)partial * SUM_SCALE);
        atomicAdd(&g_sum, q);
        __threadfence();
        const unsigned int prev = atomicAdd(&g_count, 1u);
        s_last = (prev == gridDim.x - 1);
    }
    __syncthreads();

    if (s_last && tid == 0) {
        __threadfence();
        const unsigned long long total = atomicAdd(&g_sum, 0ULL);
        out[0] = (float)(((double)total / SUM_SCALE) / (double)N);
        // reset for next graph replay
        g_sum = 0ULL;
        g_count = 0u;
    }
}

extern "C" void kernel_launch(void* const* d_in, const int* in_sizes, int n_in,
                              void* d_out, int out_size)
{
    const float* pts = (const float*)d_in[0];   // output_colors (N,3)
    const float* pal = (const float*)d_in[1];   // target_palette (M,3)
    float* out = (float*)d_out;

    const int N = in_sizes[0] / 3;
    int M = in_sizes[1] / 3;
    if (M > 2 * MAX_PAIRS) M = 2 * MAX_PAIRS;   // dataset has M=128

    long long blocks_ll = ((long long)N + (long long)TPB * PPT - 1) / ((long long)TPB * PPT);
    if (blocks_ll < 1) blocks_ll = 1;
    if (blocks_ll > 1048576) blocks_ll = 1048576;
    const int blocks = (int)blocks_ll;          // N=131072 -> 256 blocks

    ncd_fused<<<blocks, TPB>>>(pts, pal, out, N, M);
}